// round 15
// baseline (speedup 1.0000x reference)
#include <cuda_runtime.h>
#include <cuda_fp16.h>
#include <cstdint>
#include <cstddef>

// ===================== problem / tile config =====================
#define M_TOTAL 28160
#define N_TOTAL 2048
#define K_TOTAL 2048

#define BM 128
#define BN 256
#define BK 64                        // K elems per stage (128 B of data per row)
#define K_STAGES (K_TOTAL / BK)      // 32
#define STAGES 3
#define NTHREADS 256                 // 8 warps: 2 (M) x 4 (N), warp tile 64x64

// padded, UNSWIZZLED smem layout: row pitch = 128 B data + 16 B pad = 144 B
#define PITCH 144
#define A_BYTES (BM * PITCH)         // 18432
#define B_BYTES (BN * PITCH)         // 36864
#define STAGE_BYTES (A_BYTES + B_BYTES)          // 55296
#define SMEM_BYTES (STAGES * STAGE_BYTES)        // 165888 (162 KB)

#define M_TILES (M_TOTAL / BM)       // 220
#define N_TILES (N_TOTAL / BN)       // 8  (== WORLD_SIZE: ntile IS the a2a chunk)

// fp16 scratch for converted inputs
__device__ __half g_xh[(size_t)M_TOTAL * K_TOTAL];   // 115.3 MB
__device__ __half g_wh[(size_t)N_TOTAL * K_TOTAL];   // 8.4 MB

#define NX8 ((size_t)M_TOTAL * K_TOTAL / 8)
#define NW8 ((size_t)N_TOTAL * K_TOTAL / 8)

// ===================== PTX helpers (baseline sm_80-class only) =====================
static __device__ __forceinline__ uint32_t smem_u32(const void* p) {
    uint32_t a;
    asm("{ .reg .u64 t; cvta.to.shared.u64 t, %1; cvt.u32.u64 %0, t; }"
        : "=r"(a) : "l"(p));
    return a;
}

static __device__ __forceinline__ void cp_async16(uint32_t saddr, const void* gaddr) {
    asm volatile("cp.async.cg.shared.global [%0], [%1], 16;"
                 :: "r"(saddr), "l"(gaddr) : "memory");
}
#define CP_COMMIT() asm volatile("cp.async.commit_group;" ::: "memory")
#define CP_WAIT1()  asm volatile("cp.async.wait_group 1;" ::: "memory")

static __device__ __forceinline__ void ldsm_x4(uint32_t& r0, uint32_t& r1,
                                               uint32_t& r2, uint32_t& r3,
                                               uint32_t addr) {
    asm volatile("ldmatrix.sync.aligned.m8n8.x4.shared.b16 {%0,%1,%2,%3}, [%4];"
                 : "=r"(r0), "=r"(r1), "=r"(r2), "=r"(r3) : "r"(addr));
}

// fp16-accumulate HMMA (2x issue rate vs fp32-acc on this part, per theory)
static __device__ __forceinline__ void mma_16816_f16(uint32_t& c0, uint32_t& c1,
                                                     const uint32_t* a,
                                                     uint32_t b0, uint32_t b1) {
    asm volatile(
        "mma.sync.aligned.m16n8k16.row.col.f16.f16.f16.f16 "
        "{%0,%1}, {%2,%3,%4,%5}, {%6,%7}, {%0,%1};"
        : "+r"(c0), "+r"(c1)
        : "r"(a[0]), "r"(a[1]), "r"(a[2]), "r"(a[3]), "r"(b0), "r"(b1));
}

// ===================== fp32 -> fp16 convert kernel (both tensors, one launch) ===
__global__ void __launch_bounds__(256)
cvt_f2h_kernel(const float* __restrict__ xs, __half* __restrict__ xd,
               const float* __restrict__ ws, __half* __restrict__ wd) {
    const size_t total = NX8 + NW8;
    size_t i = (size_t)blockIdx.x * blockDim.x + threadIdx.x;
    const size_t stride = (size_t)gridDim.x * blockDim.x;
    for (; i < total; i += stride) {
        const float* src;
        __half* dst;
        size_t j;
        if (i < NX8) { src = xs; dst = xd; j = i; }
        else         { src = ws; dst = wd; j = i - NX8; }
        const float4 a = reinterpret_cast<const float4*>(src)[2 * j];
        const float4 b = reinterpret_cast<const float4*>(src)[2 * j + 1];
        __half2 h[4];
        h[0] = __floats2half2_rn(a.x, a.y);
        h[1] = __floats2half2_rn(a.z, a.w);
        h[2] = __floats2half2_rn(b.x, b.y);
        h[3] = __floats2half2_rn(b.z, b.w);
        reinterpret_cast<uint4*>(dst)[j] = *reinterpret_cast<uint4*>(h);
    }
}

// ===================== GEMM + fused all2all kernel =====================
// 8 warps (2x4), warp tile 64x64. K split into 32-wide windows: 2 chained
// fp16-accumulate HMMAs per window, folded into master fp32 accumulators.
__global__ void __launch_bounds__(NTHREADS, 1)
spmodel_gemm_a2a_kernel(float* __restrict__ out) {
    const __half* __restrict__ X  = g_xh;   // [M, K] fp16 row-major
    const __half* __restrict__ Wm = g_wh;   // [N, K] fp16 row-major

    extern __shared__ char smem[];
    const uint32_t sb = smem_u32(smem);
    const int tid  = threadIdx.x;
    const int lane = tid & 31;
    const int wid  = tid >> 5;

    // 8 consecutive CTAs share one A tile (hot in L2); W (8 MB) L2-resident
    const int mtile = blockIdx.x >> 3;   // / N_TILES
    const int ntile = blockIdx.x & 7;    // % N_TILES
    const int a_row = mtile * BM;
    const int b_row = ntile * BN;

    // ---- stage loader: 128 A-rows + 256 B-rows, 8 x 16B chunks per row ----
    // 256 threads: row0 = tid>>3 in [0,32), chunk cs = tid&7; 12 cp.async each
    const int row0 = tid >> 3;
    const int cs   = tid & 7;

    auto load_stage = [&](int ks, int buf) {
        const uint32_t stage = sb + (uint32_t)buf * STAGE_BYTES;
        const int kbase = ks * BK + cs * 8;               // element index
        const uint32_t coff = (uint32_t)(cs * 16);        // byte offset in row
        #pragma unroll
        for (int j = 0; j < 4; ++j) {                     // A: rows row0 + j*32
            const int r = row0 + j * 32;
            cp_async16(stage + (uint32_t)r * PITCH + coff,
                       X + (size_t)(a_row + r) * K_TOTAL + kbase);
        }
        #pragma unroll
        for (int j = 0; j < 8; ++j) {                     // B: rows row0 + j*32
            const int r = row0 + j * 32;
            cp_async16(stage + A_BYTES + (uint32_t)r * PITCH + coff,
                       Wm + (size_t)(b_row + r) * K_TOTAL + kbase);
        }
    };

    // ---- ldmatrix lane addressing ----
    const int wm = (wid >> 2) * 64;      // warp M offset (0/64)
    const int wn = (wid & 3) * 64;       // warp N offset (0/64/128/192)
    const int lrow = lane & 15;
    const int lkof = (lane >> 4) << 3;   // +8 elems for upper half-warp

    uint32_t a_base[4];
    #pragma unroll
    for (int im = 0; im < 4; ++im)
        a_base[im] = (uint32_t)(wm + im * 16 + lrow) * PITCH;
    uint32_t b_base[4];
    #pragma unroll
    for (int i2 = 0; i2 < 4; ++i2)
        b_base[i2] = (uint32_t)(wn + i2 * 16 + lrow) * PITCH;

    float acc[4][8][4];
    #pragma unroll
    for (int i = 0; i < 4; ++i)
        #pragma unroll
        for (int j = 0; j < 8; ++j)
            #pragma unroll
            for (int k = 0; k < 4; ++k) acc[i][j][k] = 0.0f;

    // ---- prologue: prefetch STAGES-1 = 2 stages ----
    load_stage(0, 0); CP_COMMIT();
    load_stage(1, 1); CP_COMMIT();

    // ---- mainloop: ONE barrier per stage; two K=32 windows per stage ----
    int bufr = 0;
    for (int ks = 0; ks < K_STAGES; ++ks) {
        CP_WAIT1();          // stage ks resident
        __syncthreads();

        const uint32_t stA = sb + (uint32_t)bufr * STAGE_BYTES;
        const uint32_t stB = stA + A_BYTES;

        const int nxt = ks + STAGES - 1;
        const int bufw = (bufr + STAGES - 1) % STAGES;
        if (nxt < K_STAGES) load_stage(nxt, bufw);
        CP_COMMIT();

        #pragma unroll
        for (int w = 0; w < 2; ++w) {        // two K=32 windows
            const uint32_t kb0 = (uint32_t)((w * 32 + lkof) * 2);
            const uint32_t kb1 = kb0 + 32;   // +16 elems

            uint32_t a[2][4][4];
            #pragma unroll
            for (int im = 0; im < 4; ++im) {
                ldsm_x4(a[0][im][0], a[0][im][1], a[0][im][2], a[0][im][3],
                        stA + a_base[im] + kb0);
                ldsm_x4(a[1][im][0], a[1][im][1], a[1][im][2], a[1][im][3],
                        stA + a_base[im] + kb1);
            }
            uint32_t b[2][4][4];
            #pragma unroll
            for (int i2 = 0; i2 < 4; ++i2) {
                ldsm_x4(b[0][i2][0], b[0][i2][1], b[0][i2][2], b[0][i2][3],
                        stB + b_base[i2] + kb0);
                ldsm_x4(b[1][i2][0], b[1][i2][1], b[1][i2][2], b[1][i2][3],
                        stB + b_base[i2] + kb1);
            }

            #pragma unroll
            for (int im = 0; im < 4; ++im) {
                #pragma unroll
                for (int in = 0; in < 8; ++in) {
                    const int i2 = in >> 1, hi = in & 1;
                    uint32_t c0 = 0, c1 = 0;     // fp16 window accumulator
                    mma_16816_f16(c0, c1, a[0][im], b[0][i2][hi], b[0][i2][hi + 2]);
                    mma_16816_f16(c0, c1, a[1][im], b[1][i2][hi], b[1][i2][hi + 2]);
                    // fold window into master fp32 accumulators
                    const float2 f0 = __half22float2(*reinterpret_cast<__half2*>(&c0));
                    const float2 f1 = __half22float2(*reinterpret_cast<__half2*>(&c1));
                    acc[im][in][0] += f0.x;
                    acc[im][in][1] += f0.y;
                    acc[im][in][2] += f1.x;
                    acc[im][in][3] += f1.y;
                }
            }
        }

        bufr = (bufr + 1 == STAGES) ? 0 : bufr + 1;
    }

    // ---- epilogue: fused all2all permutation, fp32 output ----
    // BN == 256 == one a2a chunk: w = ntile; out[(w*M_TOTAL + m)*256 + n_local]
    const int g  = lane >> 2;            // row-in-atom
    const int t2 = (lane & 3) * 2;       // col pair

    #pragma unroll
    for (int im = 0; im < 4; ++im) {
        const int m0 = a_row + wm + im * 16 + g;
        const size_t rbase = ((size_t)ntile * M_TOTAL + (size_t)m0) * 256;
        #pragma unroll
        for (int in = 0; in < 8; ++in) {
            const int c = wn + in * 8 + t2;
            float2 v01 = make_float2(acc[im][in][0], acc[im][in][1]);
            float2 v23 = make_float2(acc[im][in][2], acc[im][in][3]);
            *reinterpret_cast<float2*>(out + rbase + c)           = v01;  // row m0
            *reinterpret_cast<float2*>(out + rbase + 8 * 256 + c) = v23;  // row m0+8
        }
    }
}

// ===================== host launcher =====================
extern "C" void kernel_launch(void* const* d_in, const int* in_sizes, int n_in,
                              void* d_out, int out_size) {
    (void)n_in; (void)out_size;
    // identify x vs W by element count (x = 57,671,680 ; W = 4,194,304)
    int xi = 0, wi = 1;
    if (in_sizes[0] == N_TOTAL * K_TOTAL) { xi = 1; wi = 0; }
    const float* xf = (const float*)d_in[xi];
    const float* wf = (const float*)d_in[wi];

    static __half* xh_ptr = nullptr;
    static __half* wh_ptr = nullptr;
    static bool init_done = false;
    if (!init_done) {
        cudaGetSymbolAddress((void**)&xh_ptr, g_xh);
        cudaGetSymbolAddress((void**)&wh_ptr, g_wh);
        cudaFuncSetAttribute(spmodel_gemm_a2a_kernel,
                             cudaFuncAttributeMaxDynamicSharedMemorySize, SMEM_BYTES);
        init_done = true;
    }

    // 1) convert fp32 inputs -> fp16 scratch (single launch; lossless upcast undo)
    cvt_f2h_kernel<<<4608, 256>>>(xf, xh_ptr, wf, wh_ptr);

    // 2) GEMM + fused all2all permutation
    spmodel_gemm_a2a_kernel<<<M_TILES * N_TILES, NTHREADS, SMEM_BYTES>>>((float*)d_out);
}

// round 16
// speedup vs baseline: 1.0434x; 1.0434x over previous
#include <cuda_runtime.h>
#include <cuda_fp16.h>
#include <cstdint>
#include <cstddef>

// ===================== problem / tile config =====================
#define M_TOTAL 28160
#define N_TOTAL 2048
#define K_TOTAL 2048

#define BM 128
#define BN 256
#define BK 64                        // K elems per stage
#define K_STAGES (K_TOTAL / BK)      // 32
#define NTHREADS 512                 // 16 warps: 2 (M) x 8 (N), warp tile 64x32

// fp16 A tile: padded rows, 128 B data + 16 B pad
#define PITCH 144
#define A16_STAGE (BM * PITCH)               // 18432
#define A32_STAGE (BM * BK * 4)              // 32768 (fp32, unpadded, 256 B/row)
#define B_STAGE   (BN * PITCH)               // 36864

#define A32_OFF 0                            // ring of 2
#define A16_OFF (2 * A32_STAGE)              // 65536, ring of 2
#define B_OFF   (A16_OFF + 2 * A16_STAGE)    // 102400, ring of 3
#define SMEM_BYTES (B_OFF + 3 * B_STAGE)     // 212992 (208 KB)

#define M_TILES (M_TOTAL / BM)       // 220
#define N_TILES (N_TOTAL / BN)       // 8  (== WORLD_SIZE: ntile IS the a2a chunk)

// fp16 scratch for converted W only (x is converted inside the GEMM)
__device__ __half g_wh[(size_t)N_TOTAL * K_TOTAL];   // 8.4 MB

#define NW8 ((size_t)N_TOTAL * K_TOTAL / 8)

// ===================== PTX helpers (baseline sm_80-class only) =====================
static __device__ __forceinline__ uint32_t smem_u32(const void* p) {
    uint32_t a;
    asm("{ .reg .u64 t; cvta.to.shared.u64 t, %1; cvt.u32.u64 %0, t; }"
        : "=r"(a) : "l"(p));
    return a;
}

static __device__ __forceinline__ void cp_async16(uint32_t saddr, const void* gaddr) {
    asm volatile("cp.async.cg.shared.global [%0], [%1], 16;"
                 :: "r"(saddr), "l"(gaddr) : "memory");
}
#define CP_COMMIT() asm volatile("cp.async.commit_group;" ::: "memory")
#define CP_WAIT1()  asm volatile("cp.async.wait_group 1;" ::: "memory")

static __device__ __forceinline__ void ldsm_x4(uint32_t& r0, uint32_t& r1,
                                               uint32_t& r2, uint32_t& r3,
                                               uint32_t addr) {
    asm volatile("ldmatrix.sync.aligned.m8n8.x4.shared.b16 {%0,%1,%2,%3}, [%4];"
                 : "=r"(r0), "=r"(r1), "=r"(r2), "=r"(r3) : "r"(addr));
}

static __device__ __forceinline__ void mma_16816(float* c, const uint32_t* a,
                                                 uint32_t b0, uint32_t b1) {
    asm volatile(
        "mma.sync.aligned.m16n8k16.row.col.f32.f16.f16.f32 "
        "{%0,%1,%2,%3}, {%4,%5,%6,%7}, {%8,%9}, {%0,%1,%2,%3};"
        : "+f"(c[0]), "+f"(c[1]), "+f"(c[2]), "+f"(c[3])
        : "r"(a[0]), "r"(a[1]), "r"(a[2]), "r"(a[3]), "r"(b0), "r"(b1));
}

// ===================== fp32 -> fp16 convert kernel (W only, 8.4 MB) =====================
__global__ void __launch_bounds__(256)
cvt_w_kernel(const float* __restrict__ ws, __half* __restrict__ wd) {
    size_t i = (size_t)blockIdx.x * blockDim.x + threadIdx.x;
    const size_t stride = (size_t)gridDim.x * blockDim.x;
    for (; i < NW8; i += stride) {
        const float4 a = reinterpret_cast<const float4*>(ws)[2 * i];
        const float4 b = reinterpret_cast<const float4*>(ws)[2 * i + 1];
        __half2 h[4];
        h[0] = __floats2half2_rn(a.x, a.y);
        h[1] = __floats2half2_rn(a.z, a.w);
        h[2] = __floats2half2_rn(b.x, b.y);
        h[3] = __floats2half2_rn(b.z, b.w);
        reinterpret_cast<uint4*>(wd)[i] = *reinterpret_cast<uint4*>(h);
    }
}

// ===================== GEMM + fused x-convert + fused all2all =====================
// 16 warps (2x8), warp tile 64x32 (== R9 plateau config). A arrives as RAW FP32
// via cp.async (ring 2), converted smem->smem to fp16 PITCH-144 tiles in-loop.
__global__ void __launch_bounds__(NTHREADS, 1)
spmodel_gemm_a2a_kernel(const float* __restrict__ X32, float* __restrict__ out) {
    const __half* __restrict__ Wm = g_wh;   // [N, K] fp16 row-major

    extern __shared__ char smem[];
    const uint32_t sb = smem_u32(smem);
    const int tid  = threadIdx.x;
    const int lane = tid & 31;
    const int wid  = tid >> 5;

    // 8 consecutive CTAs share one A tile (hot in L2); W (8 MB) L2-resident
    const int mtile = blockIdx.x >> 3;   // / N_TILES
    const int ntile = blockIdx.x & 7;    // % N_TILES
    const int a_row = mtile * BM;
    const int b_row = ntile * BN;

    // ---- group loader: A32 (fp32 x) + B (fp16 W), one commit group ----
    // A32: 128 rows x 16 chunks(16B) = 2048 chunks; thread: rows (t>>4)+{0,32,64,96}, chunk t&15
    // B  : 256 rows x  8 chunks(16B) = 2048 chunks; thread: rows (t>>3)+{0,64,128,192}, chunk t&7
    const int ar0 = tid >> 4, ac = tid & 15;
    const int br0 = tid >> 3, bc = tid & 7;

    auto load_group = [&](int ks) {
        const uint32_t a32 = sb + A32_OFF + (uint32_t)(ks & 1) * A32_STAGE;
        const uint32_t bst = sb + B_OFF + (uint32_t)(ks % 3) * B_STAGE;
        const int akbase = ks * BK + ac * 4;              // fp32 elems (16 B = 4 floats)
        const int bkbase = ks * BK + bc * 8;              // fp16 elems
        #pragma unroll
        for (int j = 0; j < 4; ++j) {                     // A32 rows
            const int r = ar0 + j * 32;
            cp_async16(a32 + (uint32_t)r * (BK * 4) + (uint32_t)(ac * 16),
                       X32 + (size_t)(a_row + r) * K_TOTAL + akbase);
        }
        #pragma unroll
        for (int j = 0; j < 4; ++j) {                     // B rows
            const int r = br0 + j * 64;
            cp_async16(bst + (uint32_t)r * PITCH + (uint32_t)(bc * 16),
                       Wm + (size_t)(b_row + r) * K_TOTAL + bkbase);
        }
    };

    // ---- in-loop A convert: 512 threads x 16 floats = 128 rows x 64 elems ----
    const int crow = tid >> 2;           // [0,128)
    const int cq   = tid & 3;            // quarter: 16 floats

    // ---- ldmatrix lane addressing (identical to R9) ----
    const int wm = (wid >> 3) * 64;      // warp M offset (0/64)
    const int wn = (wid & 7) * 32;       // warp N offset (0..224)
    const int lrow = lane & 15;
    const int lkof = (lane >> 4) << 3;

    uint32_t a_base[4];
    #pragma unroll
    for (int im = 0; im < 4; ++im)
        a_base[im] = (uint32_t)(wm + im * 16 + lrow) * PITCH;
    uint32_t b_base[2];
    #pragma unroll
    for (int i2 = 0; i2 < 2; ++i2)
        b_base[i2] = (uint32_t)(wn + i2 * 16 + lrow) * PITCH;

    float acc[4][4][4];
    #pragma unroll
    for (int i = 0; i < 4; ++i)
        #pragma unroll
        for (int j = 0; j < 4; ++j)
            #pragma unroll
            for (int k = 0; k < 4; ++k) acc[i][j][k] = 0.0f;

    // ---- prologue: prefetch groups 0 and 1 ----
    load_group(0); CP_COMMIT();
    load_group(1); CP_COMMIT();

    // ---- mainloop ----
    for (int ks = 0; ks < K_STAGES; ++ks) {
        CP_WAIT1();          // group ks resident (group ks+1 may be pending)
        __syncthreads();     // A32(ks)/B(ks) visible; prior compute done

        const uint32_t a32 = sb + A32_OFF + (uint32_t)(ks & 1) * A32_STAGE;
        const uint32_t a16 = sb + A16_OFF + (uint32_t)(ks & 1) * A16_STAGE;

        // convert A32(ks) -> A16(ks): 16 floats/thread
        {
            const uint32_t src = a32 + (uint32_t)crow * (BK * 4) + (uint32_t)(cq * 64);
            const uint32_t dst = a16 + (uint32_t)crow * PITCH + (uint32_t)(cq * 32);
            float4 f0, f1, f2, f3;
            asm volatile("ld.shared.v4.f32 {%0,%1,%2,%3}, [%4];"
                         : "=f"(f0.x), "=f"(f0.y), "=f"(f0.z), "=f"(f0.w) : "r"(src));
            asm volatile("ld.shared.v4.f32 {%0,%1,%2,%3}, [%4];"
                         : "=f"(f1.x), "=f"(f1.y), "=f"(f1.z), "=f"(f1.w) : "r"(src + 16));
            asm volatile("ld.shared.v4.f32 {%0,%1,%2,%3}, [%4];"
                         : "=f"(f2.x), "=f"(f2.y), "=f"(f2.z), "=f"(f2.w) : "r"(src + 32));
            asm volatile("ld.shared.v4.f32 {%0,%1,%2,%3}, [%4];"
                         : "=f"(f3.x), "=f"(f3.y), "=f"(f3.z), "=f"(f3.w) : "r"(src + 48));
            __half2 h[8];
            h[0] = __floats2half2_rn(f0.x, f0.y); h[1] = __floats2half2_rn(f0.z, f0.w);
            h[2] = __floats2half2_rn(f1.x, f1.y); h[3] = __floats2half2_rn(f1.z, f1.w);
            h[4] = __floats2half2_rn(f2.x, f2.y); h[5] = __floats2half2_rn(f2.z, f2.w);
            h[6] = __floats2half2_rn(f3.x, f3.y); h[7] = __floats2half2_rn(f3.z, f3.w);
            const uint32_t* u = reinterpret_cast<const uint32_t*>(h);
            asm volatile("st.shared.v4.b32 [%0], {%1,%2,%3,%4};"
                         :: "r"(dst), "r"(u[0]), "r"(u[1]), "r"(u[2]), "r"(u[3]));
            asm volatile("st.shared.v4.b32 [%0], {%1,%2,%3,%4};"
                         :: "r"(dst + 16), "r"(u[4]), "r"(u[5]), "r"(u[6]), "r"(u[7]));
        }
        __syncthreads();     // A16(ks) published

        // refill: group ks+2 (A32 buf (ks)&1 now free, B buf (ks+2)%3 free)
        if (ks + 2 < K_STAGES) load_group(ks + 2);
        CP_COMMIT();

        const uint32_t stB = sb + B_OFF + (uint32_t)(ks % 3) * B_STAGE;

        #pragma unroll
        for (int kk = 0; kk < BK; kk += 16) {
            const uint32_t kbyte = (uint32_t)((kk + lkof) * 2);

            uint32_t a[4][4];
            #pragma unroll
            for (int im = 0; im < 4; ++im)
                ldsm_x4(a[im][0], a[im][1], a[im][2], a[im][3],
                        a16 + a_base[im] + kbyte);

            uint32_t b[2][4];
            #pragma unroll
            for (int i2 = 0; i2 < 2; ++i2)
                ldsm_x4(b[i2][0], b[i2][1], b[i2][2], b[i2][3],
                        stB + b_base[i2] + kbyte);

            #pragma unroll
            for (int im = 0; im < 4; ++im) {
                #pragma unroll
                for (int in = 0; in < 4; ++in) {
                    const int i2 = in >> 1, hi = in & 1;
                    mma_16816(acc[im][in], a[im], b[i2][hi], b[i2][hi + 2]);
                }
            }
        }
    }

    // ---- epilogue: fused all2all permutation, fp32 output ----
    // BN == 256 == one a2a chunk: w = ntile; out[(w*M_TOTAL + m)*256 + n_local]
    const int g  = lane >> 2;
    const int t2 = (lane & 3) * 2;

    #pragma unroll
    for (int im = 0; im < 4; ++im) {
        const int m0 = a_row + wm + im * 16 + g;
        const size_t rbase = ((size_t)ntile * M_TOTAL + (size_t)m0) * 256;
        #pragma unroll
        for (int in = 0; in < 4; ++in) {
            const int c = wn + in * 8 + t2;
            float2 v01 = make_float2(acc[im][in][0], acc[im][in][1]);
            float2 v23 = make_float2(acc[im][in][2], acc[im][in][3]);
            *reinterpret_cast<float2*>(out + rbase + c)           = v01;  // row m0
            *reinterpret_cast<float2*>(out + rbase + 8 * 256 + c) = v23;  // row m0+8
        }
    }
}

// ===================== host launcher =====================
extern "C" void kernel_launch(void* const* d_in, const int* in_sizes, int n_in,
                              void* d_out, int out_size) {
    (void)n_in; (void)out_size;
    // identify x vs W by element count (x = 57,671,680 ; W = 4,194,304)
    int xi = 0, wi = 1;
    if (in_sizes[0] == N_TOTAL * K_TOTAL) { xi = 1; wi = 0; }
    const float* xf = (const float*)d_in[xi];
    const float* wf = (const float*)d_in[wi];

    static __half* wh_ptr = nullptr;
    static bool init_done = false;
    if (!init_done) {
        cudaGetSymbolAddress((void**)&wh_ptr, g_wh);
        cudaFuncSetAttribute(spmodel_gemm_a2a_kernel,
                             cudaFuncAttributeMaxDynamicSharedMemorySize, SMEM_BYTES);
        init_done = true;
    }

    // 1) convert W only (8.4 MB, ~3 us); x is converted inside the GEMM
    cvt_w_kernel<<<512, 256>>>(wf, wh_ptr);

    // 2) GEMM (reads raw fp32 x) + fused all2all permutation
    spmodel_gemm_a2a_kernel<<<M_TILES * N_TILES, NTHREADS, SMEM_BYTES>>>(
        xf, (float*)d_out);
}

// round 17
// speedup vs baseline: 1.2965x; 1.2425x over previous
#include <cuda_runtime.h>
#include <cuda_fp16.h>
#include <cstdint>
#include <cstddef>

// ===================== problem / tile config =====================
#define M_TOTAL 28160
#define N_TOTAL 2048
#define K_TOTAL 2048

#define BM 128
#define BN 256
#define BK 64                        // K elems per stage (128 B of data per row)
#define K_STAGES (K_TOTAL / BK)      // 32
#define STAGES 4
#define NTHREADS 512                 // 16 warps: 2 (M) x 8 (N), warp tile 64x32

// padded, UNSWIZZLED smem layout: row pitch = 128 B data + 16 B pad = 144 B
#define PITCH 144
#define A_BYTES (BM * PITCH)         // 18432
#define B_BYTES (BN * PITCH)         // 36864
#define STAGE_BYTES (A_BYTES + B_BYTES)          // 55296
#define SMEM_BYTES (STAGES * STAGE_BYTES)        // 221184 (216 KB)

#define M_TILES (M_TOTAL / BM)       // 220
#define N_TILES (N_TOTAL / BN)       // 8  (== WORLD_SIZE: ntile IS the a2a chunk)

// fp16 scratch for converted inputs
__device__ __half g_xh[(size_t)M_TOTAL * K_TOTAL];   // 115.3 MB
__device__ __half g_wh[(size_t)N_TOTAL * K_TOTAL];   // 8.4 MB

#define NX8 ((size_t)M_TOTAL * K_TOTAL / 8)
#define NW8 ((size_t)N_TOTAL * K_TOTAL / 8)

// ===================== PTX helpers (baseline sm_80-class only) =====================
static __device__ __forceinline__ uint32_t smem_u32(const void* p) {
    uint32_t a;
    asm("{ .reg .u64 t; cvta.to.shared.u64 t, %1; cvt.u32.u64 %0, t; }"
        : "=r"(a) : "l"(p));
    return a;
}

static __device__ __forceinline__ void cp_async16(uint32_t saddr, const void* gaddr) {
    asm volatile("cp.async.cg.shared.global [%0], [%1], 16;"
                 :: "r"(saddr), "l"(gaddr) : "memory");
}
#define CP_COMMIT() asm volatile("cp.async.commit_group;" ::: "memory")
#define CP_WAIT2()  asm volatile("cp.async.wait_group 2;" ::: "memory")

static __device__ __forceinline__ void ldsm_x4(uint32_t& r0, uint32_t& r1,
                                               uint32_t& r2, uint32_t& r3,
                                               uint32_t addr) {
    asm volatile("ldmatrix.sync.aligned.m8n8.x4.shared.b16 {%0,%1,%2,%3}, [%4];"
                 : "=r"(r0), "=r"(r1), "=r"(r2), "=r"(r3) : "r"(addr));
}

static __device__ __forceinline__ void mma_16816(float* c, const uint32_t* a,
                                                 uint32_t b0, uint32_t b1) {
    asm volatile(
        "mma.sync.aligned.m16n8k16.row.col.f32.f16.f16.f32 "
        "{%0,%1,%2,%3}, {%4,%5,%6,%7}, {%8,%9}, {%0,%1,%2,%3};"
        : "+f"(c[0]), "+f"(c[1]), "+f"(c[2]), "+f"(c[3])
        : "r"(a[0]), "r"(a[1]), "r"(a[2]), "r"(a[3]), "r"(b0), "r"(b1));
}

// ===================== fp32 -> fp16 convert kernel (both tensors, one launch) ===
__global__ void __launch_bounds__(256)
cvt_f2h_kernel(const float* __restrict__ xs, __half* __restrict__ xd,
               const float* __restrict__ ws, __half* __restrict__ wd) {
    const size_t total = NX8 + NW8;
    size_t i = (size_t)blockIdx.x * blockDim.x + threadIdx.x;
    const size_t stride = (size_t)gridDim.x * blockDim.x;
    for (; i < total; i += stride) {
        const float* src;
        __half* dst;
        size_t j;
        if (i < NX8) { src = xs; dst = xd; j = i; }
        else         { src = ws; dst = wd; j = i - NX8; }
        const float4 a = reinterpret_cast<const float4*>(src)[2 * j];
        const float4 b = reinterpret_cast<const float4*>(src)[2 * j + 1];
        __half2 h[4];
        h[0] = __floats2half2_rn(a.x, a.y);
        h[1] = __floats2half2_rn(a.z, a.w);
        h[2] = __floats2half2_rn(b.x, b.y);
        h[3] = __floats2half2_rn(b.z, b.w);
        reinterpret_cast<uint4*>(dst)[j] = *reinterpret_cast<uint4*>(h);
    }
}

// ===================== GEMM + fused all2all kernel (R9 plateau config) =====================
// 16 warps (2x8); per-warp tile 64 (M) x 32 (N); BK=64, 4 stages, single
// barrier per stage, refill issued before compute.
__global__ void __launch_bounds__(NTHREADS, 1)
spmodel_gemm_a2a_kernel(float* __restrict__ out) {
    const __half* __restrict__ X  = g_xh;   // [M, K] fp16 row-major
    const __half* __restrict__ Wm = g_wh;   // [N, K] fp16 row-major

    extern __shared__ char smem[];
    const uint32_t sb = smem_u32(smem);
    const int tid  = threadIdx.x;
    const int lane = tid & 31;
    const int wid  = tid >> 5;

    // 8 consecutive CTAs share one A tile (hot in L2); W (8 MB) L2-resident
    const int mtile = blockIdx.x >> 3;   // / N_TILES
    const int ntile = blockIdx.x & 7;    // % N_TILES
    const int a_row = mtile * BM;
    const int b_row = ntile * BN;

    // ---- stage loader: 128 A-rows + 256 B-rows, 8 x 16B chunks per row ----
    // 512 threads: row0 = tid>>3 in [0,64), chunk cs = tid&7; 6 cp.async each
    const int row0 = tid >> 3;
    const int cs   = tid & 7;

    auto load_stage = [&](int ks) {
        const uint32_t stage = sb + (uint32_t)(ks & (STAGES - 1)) * STAGE_BYTES;
        const int kbase = ks * BK + cs * 8;               // element index
        const uint32_t coff = (uint32_t)(cs * 16);        // byte offset in row
        #pragma unroll
        for (int j = 0; j < 2; ++j) {                     // A: rows row0 + j*64
            const int r = row0 + j * 64;
            cp_async16(stage + (uint32_t)r * PITCH + coff,
                       X + (size_t)(a_row + r) * K_TOTAL + kbase);
        }
        #pragma unroll
        for (int j = 0; j < 4; ++j) {                     // B: rows row0 + j*64
            const int r = row0 + j * 64;
            cp_async16(stage + A_BYTES + (uint32_t)r * PITCH + coff,
                       Wm + (size_t)(b_row + r) * K_TOTAL + kbase);
        }
    };

    // ---- ldmatrix lane addressing ----
    const int wm = (wid >> 3) * 64;      // warp M offset (0/64)
    const int wn = (wid & 7) * 32;       // warp N offset (0..224)
    const int lrow = lane & 15;
    const int lkof = (lane >> 4) << 3;   // +8 elems for upper half-warp

    uint32_t a_base[4];
    #pragma unroll
    for (int im = 0; im < 4; ++im)
        a_base[im] = (uint32_t)(wm + im * 16 + lrow) * PITCH;
    uint32_t b_base[2];
    #pragma unroll
    for (int i2 = 0; i2 < 2; ++i2)
        b_base[i2] = (uint32_t)(wn + i2 * 16 + lrow) * PITCH;

    float acc[4][4][4];
    #pragma unroll
    for (int i = 0; i < 4; ++i)
        #pragma unroll
        for (int j = 0; j < 4; ++j)
            #pragma unroll
            for (int k = 0; k < 4; ++k) acc[i][j][k] = 0.0f;

    // ---- prologue: prefetch STAGES-1 stages ----
    #pragma unroll
    for (int s = 0; s < STAGES - 1; ++s) { load_stage(s); CP_COMMIT(); }

    // ---- mainloop: ONE barrier per stage; refill issued before compute ----
    for (int ks = 0; ks < K_STAGES; ++ks) {
        CP_WAIT2();          // stage ks resident
        __syncthreads();     // all warps done with buffer (ks+3)&3

        const uint32_t stA = sb + (uint32_t)(ks & (STAGES - 1)) * STAGE_BYTES;
        const uint32_t stB = stA + A_BYTES;

        // refill the just-freed buffer while we compute this stage
        if (ks + STAGES - 1 < K_STAGES) load_stage(ks + STAGES - 1);
        CP_COMMIT();         // one group per iteration keeps wait-count math exact

        #pragma unroll
        for (int kk = 0; kk < BK; kk += 16) {
            const uint32_t kbyte = (uint32_t)((kk + lkof) * 2);

            uint32_t a[4][4];
            #pragma unroll
            for (int im = 0; im < 4; ++im)
                ldsm_x4(a[im][0], a[im][1], a[im][2], a[im][3],
                        stA + a_base[im] + kbyte);

            // b[i2]: r0=(n0-7,k0-7) r1=(n8-15,k0-7) r2=(n0-7,k8-15) r3=(n8-15,k8-15)
            uint32_t b[2][4];
            #pragma unroll
            for (int i2 = 0; i2 < 2; ++i2)
                ldsm_x4(b[i2][0], b[i2][1], b[i2][2], b[i2][3],
                        stB + b_base[i2] + kbyte);

            #pragma unroll
            for (int im = 0; im < 4; ++im) {
                #pragma unroll
                for (int in = 0; in < 4; ++in) {
                    const int i2 = in >> 1, hi = in & 1;
                    mma_16816(acc[im][in], a[im], b[i2][hi], b[i2][hi + 2]);
                }
            }
        }
    }

    // ---- epilogue: fused all2all permutation, fp32 output ----
    // BN == 256 == one a2a chunk: w = ntile; out[(w*M_TOTAL + m)*256 + n_local]
    const int g  = lane >> 2;            // row-in-atom
    const int t2 = (lane & 3) * 2;       // col pair

    #pragma unroll
    for (int im = 0; im < 4; ++im) {
        const int m0 = a_row + wm + im * 16 + g;
        const size_t rbase = ((size_t)ntile * M_TOTAL + (size_t)m0) * 256;
        #pragma unroll
        for (int in = 0; in < 4; ++in) {
            const int c = wn + in * 8 + t2;
            float2 v01 = make_float2(acc[im][in][0], acc[im][in][1]);
            float2 v23 = make_float2(acc[im][in][2], acc[im][in][3]);
            *reinterpret_cast<float2*>(out + rbase + c)           = v01;  // row m0
            *reinterpret_cast<float2*>(out + rbase + 8 * 256 + c) = v23;  // row m0+8
        }
    }
}

// ===================== host launcher =====================
extern "C" void kernel_launch(void* const* d_in, const int* in_sizes, int n_in,
                              void* d_out, int out_size) {
    (void)n_in; (void)out_size;
    // identify x vs W by element count (x = 57,671,680 ; W = 4,194,304)
    int xi = 0, wi = 1;
    if (in_sizes[0] == N_TOTAL * K_TOTAL) { xi = 1; wi = 0; }
    const float* xf = (const float*)d_in[xi];
    const float* wf = (const float*)d_in[wi];

    static __half* xh_ptr = nullptr;
    static __half* wh_ptr = nullptr;
    static bool init_done = false;
    if (!init_done) {
        cudaGetSymbolAddress((void**)&xh_ptr, g_xh);
        cudaGetSymbolAddress((void**)&wh_ptr, g_wh);
        cudaFuncSetAttribute(spmodel_gemm_a2a_kernel,
                             cudaFuncAttributeMaxDynamicSharedMemorySize, SMEM_BYTES);
        init_done = true;
    }

    // 1) convert fp32 inputs -> fp16 scratch (single launch; lossless upcast undo)
    cvt_f2h_kernel<<<4608, 256>>>(xf, xh_ptr, wf, wh_ptr);

    // 2) GEMM + fused all2all permutation
    spmodel_gemm_a2a_kernel<<<M_TILES * N_TILES, NTHREADS, SMEM_BYTES>>>((float*)d_out);
}